// round 5
// baseline (speedup 1.0000x reference)
#include <cuda_runtime.h>
#include <cuda_bf16.h>
#include <cstdint>

#define N 8192
#define D 256
#define KE 768              // packed K: [hi|hi|lo] . [hi|lo|hi]
#define BM 128
#define BN 256
#define BK 32
#define THREADS 256
#define ITERS (KE / BK)     // 24
#define LDA 40              // smem row stride (bf16 elems), conflict-free
#define A_BYTES (BM * LDA * 2)              // 10240
#define B_BYTES (BN * LDA * 2)              // 20480
#define STAGE_BYTES (A_BYTES + B_BYTES)     // 30720
#define SMEM_BYTES (3 * STAGE_BYTES)        // 92160

// ---------------------------------------------------------------------------
__device__ __nv_bfloat16 g_pa[N * KE];   // [hi | hi | lo]
__device__ __nv_bfloat16 g_pb[N * KE];   // [hi | lo | hi]
__device__ float g_norms[N];
__device__ int   g_maxpos_i[N];          // encoded floats, INT_MIN = none
__device__ int   g_minneg_i[N];          // encoded floats, INT_MAX = none
__device__ float g_partial[32];

__device__ __forceinline__ int f2i(float f) {
    int i = __float_as_int(f);
    return i >= 0 ? i : (i ^ 0x7fffffff);
}
__device__ __forceinline__ float i2f(int i) {
    return __int_as_float(i >= 0 ? i : (i ^ 0x7fffffff));
}
__device__ __forceinline__ uint32_t smem_u32(const void* p) {
    uint32_t a;
    asm("{ .reg .u64 t; cvta.to.shared.u64 t, %1; cvt.u32.u64 %0, t; }"
        : "=r"(a) : "l"(p));
    return a;
}
__device__ __forceinline__ void cp16(uint32_t s, const void* g) {
    asm volatile("cp.async.cg.shared.global [%0], [%1], 16;\n"
                 :: "r"(s), "l"(g) : "memory");
}
#define CP_COMMIT() asm volatile("cp.async.commit_group;" ::: "memory")
#define CP_WAIT(n)  asm volatile("cp.async.wait_group %0;" :: "n"(n) : "memory")

#define LDSM_X4(r0, r1, r2, r3, a)                                            \
    asm volatile("ldmatrix.sync.aligned.m8n8.x4.shared.b16 {%0,%1,%2,%3}, [%4];" \
                 : "=r"(r0), "=r"(r1), "=r"(r2), "=r"(r3) : "r"(a))

#define MMA_BF16(c, a0, a1, a2, a3, b0, b1)                                   \
    asm volatile(                                                             \
        "mma.sync.aligned.m16n8k16.row.col.f32.bf16.bf16.f32 "                \
        "{%0,%1,%2,%3}, {%4,%5,%6,%7}, {%8,%9}, {%0,%1,%2,%3};"               \
        : "+f"((c)[0]), "+f"((c)[1]), "+f"((c)[2]), "+f"((c)[3])              \
        : "r"(a0), "r"(a1), "r"(a2), "r"(a3), "r"(b0), "r"(b1))

// ---------------------------------------------------------------------------
// Prep 1: fp32 -> packed split-bf16 operands
// ---------------------------------------------------------------------------
__global__ void convert_kernel(const float* __restrict__ feat) {
    int i = blockIdx.x * blockDim.x + threadIdx.x;   // over N*D
    if (i >= N * D) return;
    int r = i / D, c = i % D;
    float x = feat[i];
    __nv_bfloat16 h = __float2bfloat16(x);
    __nv_bfloat16 l = __float2bfloat16(x - __bfloat162float(h));
    size_t base = (size_t)r * KE + c;
    g_pa[base]         = h;
    g_pa[base + D]     = h;
    g_pa[base + 2 * D] = l;
    g_pb[base]         = h;
    g_pb[base + D]     = l;
    g_pb[base + 2 * D] = h;
}

// ---------------------------------------------------------------------------
// Prep 2: exact fp32 row norms + mining accumulator init
// ---------------------------------------------------------------------------
__global__ void norms_init_kernel(const float* __restrict__ feat) {
    int gtid = blockIdx.x * blockDim.x + threadIdx.x;
    int row = gtid >> 5;
    int lane = gtid & 31;
    if (row >= N) return;
    const float4* f = reinterpret_cast<const float4*>(feat + (size_t)row * D);
    float s = 0.f;
#pragma unroll
    for (int i = 0; i < 2; i++) {
        float4 v = f[lane + 32 * i];
        s += v.x * v.x + v.y * v.y + v.z * v.z + v.w * v.w;
    }
#pragma unroll
    for (int m = 16; m > 0; m >>= 1) s += __shfl_xor_sync(0xffffffffu, s, m);
    if (lane == 0) {
        g_norms[row] = s;
        g_maxpos_i[row] = INT_MIN;
        g_minneg_i[row] = INT_MAX;
    }
}

// ---------------------------------------------------------------------------
// Main: HMMA Gram tile (128x256), warp tile 64x64, 3-stage cp.async ring.
// Hard mining on v = cn - 2*dot (sqrt deferred to finalize).
// ---------------------------------------------------------------------------
__global__ __launch_bounds__(THREADS, 1)
void gram_kernel(const int* __restrict__ labels) {
    extern __shared__ char dsm[];
    __shared__ int   sColLab[BN];
    __shared__ float sColNorm[BN];
    __shared__ int   sRowLab[BM];
    __shared__ int   sMp[BM];
    __shared__ int   sMn[BM];

    const int tid = threadIdx.x;
    const int lane = tid & 31;
    const int wid = tid >> 5;
    const int warp_m = wid >> 2;          // 0..1  (64 rows each)
    const int warp_n = wid & 3;           // 0..3  (64 cols each)
    const int rowBase = blockIdx.x * BM;
    const int colBase = blockIdx.y * BN;

    for (int i = tid; i < BN; i += THREADS) {
        sColLab[i]  = labels[colBase + i];
        sColNorm[i] = g_norms[colBase + i];
    }
    if (tid < BM) {
        sRowLab[tid] = labels[rowBase + tid];
        sMp[tid] = INT_MIN;
        sMn[tid] = INT_MAX;
    }

    const uint32_t sbase = smem_u32(dsm);

    // per-lane ldmatrix byte offsets (within a stage)
    const uint32_t aOff = ((warp_m * 64 + (lane & 15)) * LDA + (lane >> 4) * 8) * 2;
    const uint32_t bOff = ((warp_n * 64 + (lane & 7) + ((lane >> 4) & 1) * 8) * LDA
                          + ((lane >> 3) & 1) * 8) * 2;

    const __nv_bfloat16* ga = g_pa + (size_t)rowBase * KE;
    const __nv_bfloat16* gb = g_pb + (size_t)colBase * KE;

    auto load_stage = [&](int kt, int stg) {
        const uint32_t sA = sbase + stg * STAGE_BYTES;
        const uint32_t sB = sA + A_BYTES;
        const int k0 = kt * BK;
#pragma unroll
        for (int i = 0; i < 2; i++) {               // A: 512 chunks of 16B
            int idx = tid + i * THREADS;
            int r = idx >> 2, c = idx & 3;
            cp16(sA + (r * LDA + c * 8) * 2, ga + (size_t)r * KE + k0 + c * 8);
        }
#pragma unroll
        for (int i = 0; i < 4; i++) {               // B: 1024 chunks
            int idx = tid + i * THREADS;
            int r = idx >> 2, c = idx & 3;
            cp16(sB + (r * LDA + c * 8) * 2, gb + (size_t)r * KE + k0 + c * 8);
        }
        CP_COMMIT();
    };

    float acc[4][8][4];
#pragma unroll
    for (int i = 0; i < 4; i++)
#pragma unroll
        for (int j = 0; j < 8; j++)
#pragma unroll
            for (int e = 0; e < 4; e++) acc[i][j][e] = 0.f;

    load_stage(0, 0);
    load_stage(1, 1);
    load_stage(2, 2);

    for (int it = 0; it < ITERS; ++it) {
        const int stg = it % 3;
        if (it < ITERS - 2)      { CP_WAIT(2); }
        else if (it == ITERS - 2){ CP_WAIT(1); }
        else                     { CP_WAIT(0); }
        __syncthreads();

        const uint32_t sA = sbase + stg * STAGE_BYTES;
        const uint32_t sB = sA + A_BYTES;
#pragma unroll
        for (int ks = 0; ks < 2; ks++) {            // two k16 steps per BK=32
            uint32_t aF[4][4], bF[4][4];
#pragma unroll
            for (int mt = 0; mt < 4; mt++)
                LDSM_X4(aF[mt][0], aF[mt][1], aF[mt][2], aF[mt][3],
                        sA + aOff + mt * (16 * LDA * 2) + ks * 32);
#pragma unroll
            for (int ng = 0; ng < 4; ng++)
                LDSM_X4(bF[ng][0], bF[ng][1], bF[ng][2], bF[ng][3],
                        sB + bOff + ng * (16 * LDA * 2) + ks * 32);
#pragma unroll
            for (int mt = 0; mt < 4; mt++) {
#pragma unroll
                for (int nt = 0; nt < 8; nt++) {
                    const int ng = nt >> 1;
                    const int hi = (nt & 1) << 1;
                    MMA_BF16(acc[mt][nt], aF[mt][0], aF[mt][1], aF[mt][2], aF[mt][3],
                             bF[ng][hi], bF[ng][hi + 1]);
                }
            }
        }
        __syncthreads();
        if (it + 3 < ITERS) load_stage(it + 3, stg);
    }

    // ---- epilogue: hard mining on v = cn - 2*dot ----
    {
        float cn16[16]; int clab16[16], gcol16[16];
#pragma unroll
        for (int nt = 0; nt < 8; nt++)
#pragma unroll
            for (int e = 0; e < 2; e++) {
                int cc = warp_n * 64 + nt * 8 + (lane & 3) * 2 + e;
                cn16[nt * 2 + e] = sColNorm[cc];
                clab16[nt * 2 + e] = sColLab[cc];
                gcol16[nt * 2 + e] = colBase + cc;
            }
        int rl8[8], grow8[8];
#pragma unroll
        for (int mt = 0; mt < 4; mt++)
#pragma unroll
            for (int h = 0; h < 2; h++) {
                int rr = warp_m * 64 + mt * 16 + (lane >> 2) + h * 8;
                rl8[mt * 2 + h] = sRowLab[rr];
                grow8[mt * 2 + h] = rowBase + rr;
            }

        float mp[8], mn[8];
#pragma unroll
        for (int i = 0; i < 8; i++) { mp[i] = -3.0e38f; mn[i] = 3.0e38f; }

#pragma unroll
        for (int mt = 0; mt < 4; mt++)
#pragma unroll
            for (int h = 0; h < 2; h++) {
                const int ri = mt * 2 + h;
#pragma unroll
                for (int nt = 0; nt < 8; nt++)
#pragma unroll
                    for (int e = 0; e < 2; e++) {
                        const int ci = nt * 2 + e;
                        float v = fmaf(-2.f, acc[mt][nt][h * 2 + e], cn16[ci]);
                        bool same = (rl8[ri] == clab16[ci]);
                        if (same) {
                            if (grow8[ri] != gcol16[ci]) mp[ri] = fmaxf(mp[ri], v);
                        } else {
                            mn[ri] = fminf(mn[ri], v);
                        }
                    }
            }

        // reduce across the 4 lanes sharing each row
#pragma unroll
        for (int i = 0; i < 8; i++) {
#pragma unroll
            for (int m = 1; m < 4; m <<= 1) {
                mp[i] = fmaxf(mp[i], __shfl_xor_sync(0xffffffffu, mp[i], m));
                mn[i] = fminf(mn[i], __shfl_xor_sync(0xffffffffu, mn[i], m));
            }
        }
        if ((lane & 3) == 0) {
#pragma unroll
            for (int mt = 0; mt < 4; mt++)
#pragma unroll
                for (int h = 0; h < 2; h++) {
                    int rr = warp_m * 64 + mt * 16 + (lane >> 2) + h * 8;
                    float vp = mp[mt * 2 + h], vn = mn[mt * 2 + h];
                    if (vp > -2.9e38f) atomicMax(&sMp[rr], f2i(vp));
                    if (vn <  2.9e38f) atomicMin(&sMn[rr], f2i(vn));
                }
        }
    }
    __syncthreads();
    if (tid < BM) {
        if (sMp[tid] != INT_MIN) atomicMax(&g_maxpos_i[rowBase + tid], sMp[tid]);
        if (sMn[tid] != INT_MAX) atomicMin(&g_minneg_i[rowBase + tid], sMn[tid]);
    }
}

// ---------------------------------------------------------------------------
// Finalize: per-row sqrt + margin, deterministic two-phase mean
// ---------------------------------------------------------------------------
__global__ void finalize1_kernel() {
    __shared__ float ssum[256];
    int t = threadIdx.x;
    int r = blockIdx.x * 256 + t;
    float rn = g_norms[r];
    int ep = g_maxpos_i[r];
    int en = g_minneg_i[r];
    float ap = (ep == INT_MIN) ? 0.f : sqrtf(fmaxf(rn + i2f(ep), 0.f));
    float an = (en == INT_MAX) ? 1e6f : sqrtf(fmaxf(rn + i2f(en), 0.f));
    ssum[t] = fmaxf(0.f, 0.3f + ap - an);
    __syncthreads();
    for (int off = 128; off > 0; off >>= 1) {
        if (t < off) ssum[t] += ssum[t + off];
        __syncthreads();
    }
    if (t == 0) g_partial[blockIdx.x] = ssum[0];
}
__global__ void finalize2_kernel(float* __restrict__ out) {
    float v = g_partial[threadIdx.x];
#pragma unroll
    for (int m = 16; m > 0; m >>= 1) v += __shfl_xor_sync(0xffffffffu, v, m);
    if (threadIdx.x == 0) out[0] = v / (float)N;
}

// ---------------------------------------------------------------------------
extern "C" void kernel_launch(void* const* d_in, const int* in_sizes, int n_in,
                              void* d_out, int out_size) {
    const float* feat = (const float*)d_in[0];
    const int* labels = (const int*)d_in[1];
    float* out = (float*)d_out;

    cudaFuncSetAttribute(gram_kernel,
                         cudaFuncAttributeMaxDynamicSharedMemorySize, SMEM_BYTES);

    convert_kernel<<<(N * D + 255) / 256, 256>>>(feat);
    norms_init_kernel<<<(N * 32 + 255) / 256, 256>>>(feat);
    gram_kernel<<<dim3(N / BM, N / BN), THREADS, SMEM_BYTES>>>(labels);
    finalize1_kernel<<<N / 256, 256>>>();
    finalize2_kernel<<<1, 32>>>(out);
}

// round 6
// speedup vs baseline: 1.9617x; 1.9617x over previous
#include <cuda_runtime.h>
#include <cuda_bf16.h>
#include <cstdint>

#define N 8192
#define D 256
#define KE 768              // packed K: [hi|hi|lo] . [hi|lo|hi]
#define BM 128
#define BN 128
#define BK 32
#define THREADS 256
#define ITERS (KE / BK)     // 24
#define NTILE (N / BM)      // 64
#define NBLOCKS (NTILE * (NTILE + 1) / 2)   // 2080

// ---------------------------------------------------------------------------
__device__ __nv_bfloat16 g_pa[N * KE];   // [hi | hi | lo]
__device__ __nv_bfloat16 g_pb[N * KE];   // [hi | lo | hi]
__device__ float g_norms[N];
__device__ int   g_maxpos_i[N];          // encoded floats, INT_MIN = none
__device__ int   g_minneg_i[N];          // encoded floats, INT_MAX = none
__device__ float g_partial[32];

__device__ __forceinline__ int f2i(float f) {
    int i = __float_as_int(f);
    return i >= 0 ? i : (i ^ 0x7fffffff);
}
__device__ __forceinline__ float i2f(int i) {
    return __int_as_float(i >= 0 ? i : (i ^ 0x7fffffff));
}
__device__ __forceinline__ uint32_t smem_u32(const void* p) {
    uint32_t a;
    asm("{ .reg .u64 t; cvta.to.shared.u64 t, %1; cvt.u32.u64 %0, t; }"
        : "=r"(a) : "l"(p));
    return a;
}
__device__ __forceinline__ void cp16(uint32_t s, const void* g) {
    asm volatile("cp.async.cg.shared.global [%0], [%1], 16;\n"
                 :: "r"(s), "l"(g) : "memory");
}
#define CP_COMMIT() asm volatile("cp.async.commit_group;" ::: "memory")
#define CP_WAIT(n)  asm volatile("cp.async.wait_group %0;" :: "n"(n) : "memory")

#define LDSM_X4(r0, r1, r2, r3, a)                                            \
    asm volatile("ldmatrix.sync.aligned.m8n8.x4.shared.b16 {%0,%1,%2,%3}, [%4];" \
                 : "=r"(r0), "=r"(r1), "=r"(r2), "=r"(r3) : "r"(a))

#define MMA_BF16(c, a0, a1, a2, a3, b0, b1)                                   \
    asm volatile(                                                             \
        "mma.sync.aligned.m16n8k16.row.col.f32.bf16.bf16.f32 "                \
        "{%0,%1,%2,%3}, {%4,%5,%6,%7}, {%8,%9}, {%0,%1,%2,%3};"               \
        : "+f"((c)[0]), "+f"((c)[1]), "+f"((c)[2]), "+f"((c)[3])              \
        : "r"(a0), "r"(a1), "r"(a2), "r"(a3), "r"(b0), "r"(b1))

// ---------------------------------------------------------------------------
// Prep 1: fp32 -> packed split-bf16 operands
// ---------------------------------------------------------------------------
__global__ void convert_kernel(const float* __restrict__ feat) {
    int i = blockIdx.x * blockDim.x + threadIdx.x;   // over N*D
    if (i >= N * D) return;
    int r = i / D, c = i % D;
    float x = feat[i];
    __nv_bfloat16 h = __float2bfloat16(x);
    __nv_bfloat16 l = __float2bfloat16(x - __bfloat162float(h));
    size_t base = (size_t)r * KE + c;
    g_pa[base]         = h;
    g_pa[base + D]     = h;
    g_pa[base + 2 * D] = l;
    g_pb[base]         = h;
    g_pb[base + D]     = l;
    g_pb[base + 2 * D] = h;
}

// ---------------------------------------------------------------------------
// Prep 2: exact fp32 row norms + mining accumulator init
// ---------------------------------------------------------------------------
__global__ void norms_init_kernel(const float* __restrict__ feat) {
    int gtid = blockIdx.x * blockDim.x + threadIdx.x;
    int row = gtid >> 5;
    int lane = gtid & 31;
    if (row >= N) return;
    const float4* f = reinterpret_cast<const float4*>(feat + (size_t)row * D);
    float s = 0.f;
#pragma unroll
    for (int i = 0; i < 2; i++) {
        float4 v = f[lane + 32 * i];
        s += v.x * v.x + v.y * v.y + v.z * v.z + v.w * v.w;
    }
#pragma unroll
    for (int m = 16; m > 0; m >>= 1) s += __shfl_xor_sync(0xffffffffu, s, m);
    if (lane == 0) {
        g_norms[row] = s;
        g_maxpos_i[row] = INT_MIN;
        g_minneg_i[row] = INT_MAX;
    }
}

// ---------------------------------------------------------------------------
// Main: symmetric HMMA Gram (upper-tri tiles only) + dual-orientation mining
// ---------------------------------------------------------------------------
#define LDA 40

__global__ __launch_bounds__(THREADS, 2)
void gram_kernel(const int* __restrict__ labels) {
    __shared__ __nv_bfloat16 As[2][BM * LDA];
    __shared__ __nv_bfloat16 Bs[2][BN * LDA];
    __shared__ int   sColLab[BN];
    __shared__ float sColNorm[BN];
    __shared__ int   sRowLab[BM];
    __shared__ float sRowNorm[BM];
    __shared__ int   sMp[BM],  sMn[BM];    // row-wise results (tile I rows)
    __shared__ int   sMp2[BN], sMn2[BN];   // col-wise results (tile J rows)

    // decode upper-triangular tile pair (I <= J)
    int t = blockIdx.x;
    int I = 0;
    while (t >= NTILE - I) { t -= NTILE - I; I++; }
    const int J = I + t;
    const bool offdiag = (I != J);
    const int rowBase = I * BM;
    const int colBase = J * BN;

    const int tid = threadIdx.x;
    const int lane = tid & 31;
    const int wid = tid >> 5;
    const int warp_m = wid >> 2;          // 0..1  (64 rows each)
    const int warp_n = wid & 3;           // 0..3  (32 cols each)

    if (tid < BM) {
        sColLab[tid]  = labels[colBase + tid];
        sColNorm[tid] = g_norms[colBase + tid];
        sRowLab[tid]  = labels[rowBase + tid];
        sRowNorm[tid] = g_norms[rowBase + tid];
        sMp[tid] = INT_MIN;  sMn[tid] = INT_MAX;
        sMp2[tid] = INT_MIN; sMn2[tid] = INT_MAX;
    }

    const uint32_t sA[2] = {smem_u32(&As[0][0]), smem_u32(&As[1][0])};
    const uint32_t sB[2] = {smem_u32(&Bs[0][0]), smem_u32(&Bs[1][0])};

    const uint32_t aOff = ((warp_m * 64 + (lane & 15)) * LDA + (lane >> 4) * 8) * 2;
    const uint32_t bOff = ((warp_n * 32 + (lane & 7) + ((lane >> 4) & 1) * 8) * LDA
                          + ((lane >> 3) & 1) * 8) * 2;

    const __nv_bfloat16* ga = g_pa + (size_t)rowBase * KE;
    const __nv_bfloat16* gb = g_pb + (size_t)colBase * KE;

    auto load_stage = [&](int kt, int buf) {
        const int k0 = kt * BK;
#pragma unroll
        for (int i = 0; i < 2; i++) {
            int idx = tid + i * THREADS;
            int r = idx >> 2, c = idx & 3;
            cp16(sA[buf] + (r * LDA + c * 8) * 2, ga + (size_t)r * KE + k0 + c * 8);
        }
#pragma unroll
        for (int i = 0; i < 2; i++) {
            int idx = tid + i * THREADS;
            int r = idx >> 2, c = idx & 3;
            cp16(sB[buf] + (r * LDA + c * 8) * 2, gb + (size_t)r * KE + k0 + c * 8);
        }
        CP_COMMIT();
    };

    float acc[4][4][4];
#pragma unroll
    for (int i = 0; i < 4; i++)
#pragma unroll
        for (int j = 0; j < 4; j++)
#pragma unroll
            for (int e = 0; e < 4; e++) acc[i][j][e] = 0.f;

    load_stage(0, 0);

    for (int it = 0; it < ITERS; ++it) {
        const int buf = it & 1;
        if (it + 1 < ITERS) load_stage(it + 1, buf ^ 1);
        if (it + 1 < ITERS) { CP_WAIT(1); } else { CP_WAIT(0); }
        __syncthreads();

#pragma unroll
        for (int ks = 0; ks < 2; ks++) {
            uint32_t aF[4][4], bF[2][4];
#pragma unroll
            for (int mt = 0; mt < 4; mt++)
                LDSM_X4(aF[mt][0], aF[mt][1], aF[mt][2], aF[mt][3],
                        sA[buf] + aOff + mt * (16 * LDA * 2) + ks * 32);
#pragma unroll
            for (int ng = 0; ng < 2; ng++)
                LDSM_X4(bF[ng][0], bF[ng][1], bF[ng][2], bF[ng][3],
                        sB[buf] + bOff + ng * (16 * LDA * 2) + ks * 32);
#pragma unroll
            for (int mt = 0; mt < 4; mt++) {
#pragma unroll
                for (int nt = 0; nt < 4; nt++) {
                    const int ng = nt >> 1;
                    const int hi = (nt & 1) << 1;
                    MMA_BF16(acc[mt][nt], aF[mt][0], aF[mt][1], aF[mt][2], aF[mt][3],
                             bF[ng][hi], bF[ng][hi + 1]);
                }
            }
        }
        __syncthreads();
    }

    // ---- epilogue ----
    {
        float cn8[8]; int clab8[8];
#pragma unroll
        for (int nt = 0; nt < 4; nt++)
#pragma unroll
            for (int e = 0; e < 2; e++) {
                int cc = warp_n * 32 + nt * 8 + (lane & 3) * 2 + e;
                cn8[nt * 2 + e] = sColNorm[cc];
                clab8[nt * 2 + e] = sColLab[cc];
            }
        int rl8[8]; float rn8[8]; int rr8[8];
#pragma unroll
        for (int mt = 0; mt < 4; mt++)
#pragma unroll
            for (int h = 0; h < 2; h++) {
                int rr = warp_m * 64 + mt * 16 + (lane >> 2) + h * 8;
                rr8[mt * 2 + h] = rr;
                rl8[mt * 2 + h] = sRowLab[rr];
                rn8[mt * 2 + h] = sRowNorm[rr];
            }

        // --- row-wise mining: v = cn - 2*dot ---
        float mp[8], mn[8];
#pragma unroll
        for (int i = 0; i < 8; i++) { mp[i] = -3.0e38f; mn[i] = 3.0e38f; }
#pragma unroll
        for (int mt = 0; mt < 4; mt++)
#pragma unroll
            for (int h = 0; h < 2; h++) {
                const int ri = mt * 2 + h;
#pragma unroll
                for (int nt = 0; nt < 4; nt++)
#pragma unroll
                    for (int e = 0; e < 2; e++) {
                        const int ci = nt * 2 + e;
                        float v = fmaf(-2.f, acc[mt][nt][h * 2 + e], cn8[ci]);
                        bool same = (rl8[ri] == clab8[ci]);
                        // self-pair only possible on diagonal tiles
                        bool self = !offdiag &&
                            (rr8[ri] == warp_n * 32 + nt * 8 + (lane & 3) * 2 + e);
                        if (same) {
                            if (!self) mp[ri] = fmaxf(mp[ri], v);
                        } else {
                            mn[ri] = fminf(mn[ri], v);
                        }
                    }
            }
#pragma unroll
        for (int i = 0; i < 8; i++) {
#pragma unroll
            for (int m = 1; m < 4; m <<= 1) {
                mp[i] = fmaxf(mp[i], __shfl_xor_sync(0xffffffffu, mp[i], m));
                mn[i] = fminf(mn[i], __shfl_xor_sync(0xffffffffu, mn[i], m));
            }
        }
        if ((lane & 3) == 0) {
#pragma unroll
            for (int i = 0; i < 8; i++) {
                if (mp[i] > -2.9e38f) atomicMax(&sMp[rr8[i]], f2i(mp[i]));
                if (mn[i] <  2.9e38f) atomicMin(&sMn[rr8[i]], f2i(mn[i]));
            }
        }

        // --- column-wise mining (off-diagonal only): v' = rn - 2*dot ---
        if (offdiag) {
            float mpc[8], mnc[8];
#pragma unroll
            for (int i = 0; i < 8; i++) { mpc[i] = -3.0e38f; mnc[i] = 3.0e38f; }
#pragma unroll
            for (int nt = 0; nt < 4; nt++)
#pragma unroll
                for (int e = 0; e < 2; e++) {
                    const int ci = nt * 2 + e;
#pragma unroll
                    for (int mt = 0; mt < 4; mt++)
#pragma unroll
                        for (int h = 0; h < 2; h++) {
                            const int ri = mt * 2 + h;
                            float v = fmaf(-2.f, acc[mt][nt][h * 2 + e], rn8[ri]);
                            if (rl8[ri] == clab8[ci]) mpc[ci] = fmaxf(mpc[ci], v);
                            else                       mnc[ci] = fminf(mnc[ci], v);
                        }
                }
            // reduce across the 8 lanes sharing each column (lane>>2 varies)
#pragma unroll
            for (int i = 0; i < 8; i++) {
#pragma unroll
                for (int m = 4; m < 32; m <<= 1) {
                    mpc[i] = fmaxf(mpc[i], __shfl_xor_sync(0xffffffffu, mpc[i], m));
                    mnc[i] = fminf(mnc[i], __shfl_xor_sync(0xffffffffu, mnc[i], m));
                }
            }
            if (lane < 4) {
#pragma unroll
                for (int nt = 0; nt < 4; nt++)
#pragma unroll
                    for (int e = 0; e < 2; e++) {
                        int cc = warp_n * 32 + nt * 8 + lane * 2 + e;
                        const int ci = nt * 2 + e;
                        if (mpc[ci] > -2.9e38f) atomicMax(&sMp2[cc], f2i(mpc[ci]));
                        if (mnc[ci] <  2.9e38f) atomicMin(&sMn2[cc], f2i(mnc[ci]));
                    }
            }
        }
    }
    __syncthreads();
    if (tid < BM) {
        if (sMp[tid] != INT_MIN) atomicMax(&g_maxpos_i[rowBase + tid], sMp[tid]);
        if (sMn[tid] != INT_MAX) atomicMin(&g_minneg_i[rowBase + tid], sMn[tid]);
        if (offdiag) {
            if (sMp2[tid] != INT_MIN) atomicMax(&g_maxpos_i[colBase + tid], sMp2[tid]);
            if (sMn2[tid] != INT_MAX) atomicMin(&g_minneg_i[colBase + tid], sMn2[tid]);
        }
    }
}

// ---------------------------------------------------------------------------
// Finalize: per-row sqrt + margin, deterministic two-phase mean
// ---------------------------------------------------------------------------
__global__ void finalize1_kernel() {
    __shared__ float ssum[256];
    int t = threadIdx.x;
    int r = blockIdx.x * 256 + t;
    float rn = g_norms[r];
    int ep = g_maxpos_i[r];
    int en = g_minneg_i[r];
    float ap = (ep == INT_MIN) ? 0.f : sqrtf(fmaxf(rn + i2f(ep), 0.f));
    float an = (en == INT_MAX) ? 1e6f : sqrtf(fmaxf(rn + i2f(en), 0.f));
    ssum[t] = fmaxf(0.f, 0.3f + ap - an);
    __syncthreads();
    for (int off = 128; off > 0; off >>= 1) {
        if (t < off) ssum[t] += ssum[t + off];
        __syncthreads();
    }
    if (t == 0) g_partial[blockIdx.x] = ssum[0];
}
__global__ void finalize2_kernel(float* __restrict__ out) {
    float v = g_partial[threadIdx.x];
#pragma unroll
    for (int m = 16; m > 0; m >>= 1) v += __shfl_xor_sync(0xffffffffu, v, m);
    if (threadIdx.x == 0) out[0] = v / (float)N;
}

// ---------------------------------------------------------------------------
extern "C" void kernel_launch(void* const* d_in, const int* in_sizes, int n_in,
                              void* d_out, int out_size) {
    const float* feat = (const float*)d_in[0];
    const int* labels = (const int*)d_in[1];
    float* out = (float*)d_out;

    convert_kernel<<<(N * D + 255) / 256, 256>>>(feat);
    norms_init_kernel<<<(N * 32 + 255) / 256, 256>>>(feat);
    gram_kernel<<<NBLOCKS, THREADS>>>(labels);
    finalize1_kernel<<<N / 256, 256>>>();
    finalize2_kernel<<<1, 32>>>(out);
}

// round 7
// speedup vs baseline: 3.0845x; 1.5724x over previous
#include <cuda_runtime.h>
#include <cuda_fp16.h>
#include <cstdint>

#define N 8192
#define D 256
#define KE 512              // [hi|lo] . [hi|hi]  (fp16 split, one cross term)
#define BM 128
#define BN 128
#define BK 32
#define THREADS 256
#define ITERS (KE / BK)     // 16
#define NTILE (N / BM)      // 64
#define NBLOCKS (NTILE * (NTILE + 1) / 2)   // 2080

// ---------------------------------------------------------------------------
__device__ __half g_hi[N * D];
__device__ __half g_lo[N * D];
__device__ float g_norms[N];
__device__ int   g_maxpos_i[N];          // encoded floats, INT_MIN = none
__device__ int   g_minneg_i[N];          // encoded floats, INT_MAX = none
__device__ float g_partial[32];

__device__ __forceinline__ int f2i(float f) {
    int i = __float_as_int(f);
    return i >= 0 ? i : (i ^ 0x7fffffff);
}
__device__ __forceinline__ float i2f(int i) {
    return __int_as_float(i >= 0 ? i : (i ^ 0x7fffffff));
}
__device__ __forceinline__ uint32_t smem_u32(const void* p) {
    uint32_t a;
    asm("{ .reg .u64 t; cvta.to.shared.u64 t, %1; cvt.u32.u64 %0, t; }"
        : "=r"(a) : "l"(p));
    return a;
}
__device__ __forceinline__ void cp16(uint32_t s, const void* g) {
    asm volatile("cp.async.cg.shared.global [%0], [%1], 16;\n"
                 :: "r"(s), "l"(g) : "memory");
}
#define CP_COMMIT() asm volatile("cp.async.commit_group;" ::: "memory")
#define CP_WAIT(n)  asm volatile("cp.async.wait_group %0;" :: "n"(n) : "memory")

#define LDSM_X4(r0, r1, r2, r3, a)                                            \
    asm volatile("ldmatrix.sync.aligned.m8n8.x4.shared.b16 {%0,%1,%2,%3}, [%4];" \
                 : "=r"(r0), "=r"(r1), "=r"(r2), "=r"(r3) : "r"(a))

#define MMA_F16(c, a0, a1, a2, a3, b0, b1)                                    \
    asm volatile(                                                             \
        "mma.sync.aligned.m16n8k16.row.col.f32.f16.f16.f32 "                  \
        "{%0,%1,%2,%3}, {%4,%5,%6,%7}, {%8,%9}, {%0,%1,%2,%3};"               \
        : "+f"((c)[0]), "+f"((c)[1]), "+f"((c)[2]), "+f"((c)[3])              \
        : "r"(a0), "r"(a1), "r"(a2), "r"(a3), "r"(b0), "r"(b1))

// ---------------------------------------------------------------------------
// Prep 1: fp32 -> (hi, lo) fp16 split
// ---------------------------------------------------------------------------
__global__ void convert_kernel(const float* __restrict__ feat) {
    int i = blockIdx.x * blockDim.x + threadIdx.x;   // over N*D/4
    if (i >= N * D / 4) return;
    float4 v = reinterpret_cast<const float4*>(feat)[i];
    float x[4] = {v.x, v.y, v.z, v.w};
    __half h[4], l[4];
#pragma unroll
    for (int j = 0; j < 4; j++) {
        h[j] = __float2half_rn(x[j]);
        l[j] = __float2half_rn(x[j] - __half2float(h[j]));
    }
    *reinterpret_cast<uint2*>(g_hi + (size_t)i * 4) = *reinterpret_cast<uint2*>(h);
    *reinterpret_cast<uint2*>(g_lo + (size_t)i * 4) = *reinterpret_cast<uint2*>(l);
}

// ---------------------------------------------------------------------------
// Prep 2: exact fp32 row norms + mining accumulator init
// ---------------------------------------------------------------------------
__global__ void norms_init_kernel(const float* __restrict__ feat) {
    int gtid = blockIdx.x * blockDim.x + threadIdx.x;
    int row = gtid >> 5;
    int lane = gtid & 31;
    if (row >= N) return;
    const float4* f = reinterpret_cast<const float4*>(feat + (size_t)row * D);
    float s = 0.f;
#pragma unroll
    for (int i = 0; i < 2; i++) {
        float4 v = f[lane + 32 * i];
        s += v.x * v.x + v.y * v.y + v.z * v.z + v.w * v.w;
    }
#pragma unroll
    for (int m = 16; m > 0; m >>= 1) s += __shfl_xor_sync(0xffffffffu, s, m);
    if (lane == 0) {
        g_norms[row] = s;
        g_maxpos_i[row] = INT_MIN;
        g_minneg_i[row] = INT_MAX;
    }
}

// ---------------------------------------------------------------------------
// Main: symmetric HMMA Gram (upper-tri tiles only) + dual-orientation mining
// A k-chunks 0..7 read hi, 8..15 read lo; B always reads hi (k mod 256).
// ---------------------------------------------------------------------------
#define LDA 40

__global__ __launch_bounds__(THREADS, 2)
void gram_kernel(const int* __restrict__ labels) {
    __shared__ __half As[2][BM * LDA];
    __shared__ __half Bs[2][BN * LDA];
    __shared__ int   sColLab[BN];
    __shared__ float sColNorm[BN];
    __shared__ int   sRowLab[BM];
    __shared__ float sRowNorm[BM];
    __shared__ int   sMp[BM],  sMn[BM];    // row-wise results (tile I rows)
    __shared__ int   sMp2[BN], sMn2[BN];   // col-wise results (tile J rows)

    // decode upper-triangular tile pair (I <= J)
    int t = blockIdx.x;
    int I = 0;
    while (t >= NTILE - I) { t -= NTILE - I; I++; }
    const int J = I + t;
    const bool offdiag = (I != J);
    const int rowBase = I * BM;
    const int colBase = J * BN;

    const int tid = threadIdx.x;
    const int lane = tid & 31;
    const int wid = tid >> 5;
    const int warp_m = wid >> 2;          // 0..1  (64 rows each)
    const int warp_n = wid & 3;           // 0..3  (32 cols each)

    if (tid < BM) {
        sColLab[tid]  = labels[colBase + tid];
        sColNorm[tid] = g_norms[colBase + tid];
        sRowLab[tid]  = labels[rowBase + tid];
        sRowNorm[tid] = g_norms[rowBase + tid];
        sMp[tid] = INT_MIN;  sMn[tid] = INT_MAX;
        sMp2[tid] = INT_MIN; sMn2[tid] = INT_MAX;
    }

    const uint32_t sA[2] = {smem_u32(&As[0][0]), smem_u32(&As[1][0])};
    const uint32_t sB[2] = {smem_u32(&Bs[0][0]), smem_u32(&Bs[1][0])};

    const uint32_t aOff = ((warp_m * 64 + (lane & 15)) * LDA + (lane >> 4) * 8) * 2;
    const uint32_t bOff = ((warp_n * 32 + (lane & 7) + ((lane >> 4) & 1) * 8) * LDA
                          + ((lane >> 3) & 1) * 8) * 2;

    auto load_stage = [&](int kt, int buf) {
        const int k0 = (kt & 7) * BK;
        const __half* ga = (kt < 8 ? g_hi : g_lo) + (size_t)rowBase * D;
        const __half* gb = g_hi + (size_t)colBase * D;
#pragma unroll
        for (int i = 0; i < 2; i++) {
            int idx = tid + i * THREADS;
            int r = idx >> 2, c = idx & 3;
            cp16(sA[buf] + (r * LDA + c * 8) * 2, ga + (size_t)r * D + k0 + c * 8);
        }
#pragma unroll
        for (int i = 0; i < 2; i++) {
            int idx = tid + i * THREADS;
            int r = idx >> 2, c = idx & 3;
            cp16(sB[buf] + (r * LDA + c * 8) * 2, gb + (size_t)r * D + k0 + c * 8);
        }
        CP_COMMIT();
    };

    float acc[4][4][4];
#pragma unroll
    for (int i = 0; i < 4; i++)
#pragma unroll
        for (int j = 0; j < 4; j++)
#pragma unroll
            for (int e = 0; e < 4; e++) acc[i][j][e] = 0.f;

    load_stage(0, 0);

    for (int it = 0; it < ITERS; ++it) {
        const int buf = it & 1;
        if (it + 1 < ITERS) load_stage(it + 1, buf ^ 1);
        if (it + 1 < ITERS) { CP_WAIT(1); } else { CP_WAIT(0); }
        __syncthreads();

#pragma unroll
        for (int ks = 0; ks < 2; ks++) {
            uint32_t aF[4][4], bF[2][4];
#pragma unroll
            for (int mt = 0; mt < 4; mt++)
                LDSM_X4(aF[mt][0], aF[mt][1], aF[mt][2], aF[mt][3],
                        sA[buf] + aOff + mt * (16 * LDA * 2) + ks * 32);
#pragma unroll
            for (int ng = 0; ng < 2; ng++)
                LDSM_X4(bF[ng][0], bF[ng][1], bF[ng][2], bF[ng][3],
                        sB[buf] + bOff + ng * (16 * LDA * 2) + ks * 32);
#pragma unroll
            for (int mt = 0; mt < 4; mt++) {
#pragma unroll
                for (int nt = 0; nt < 4; nt++) {
                    const int ng = nt >> 1;
                    const int hi = (nt & 1) << 1;
                    MMA_F16(acc[mt][nt], aF[mt][0], aF[mt][1], aF[mt][2], aF[mt][3],
                            bF[ng][hi], bF[ng][hi + 1]);
                }
            }
        }
        __syncthreads();
    }

    // ---- epilogue ----
    {
        float cn8[8]; int clab8[8];
#pragma unroll
        for (int nt = 0; nt < 4; nt++)
#pragma unroll
            for (int e = 0; e < 2; e++) {
                int cc = warp_n * 32 + nt * 8 + (lane & 3) * 2 + e;
                cn8[nt * 2 + e] = sColNorm[cc];
                clab8[nt * 2 + e] = sColLab[cc];
            }
        int rl8[8]; float rn8[8]; int rr8[8];
#pragma unroll
        for (int mt = 0; mt < 4; mt++)
#pragma unroll
            for (int h = 0; h < 2; h++) {
                int rr = warp_m * 64 + mt * 16 + (lane >> 2) + h * 8;
                rr8[mt * 2 + h] = rr;
                rl8[mt * 2 + h] = sRowLab[rr];
                rn8[mt * 2 + h] = sRowNorm[rr];
            }

        // --- row-wise mining: v = cn - 2*dot ---
        float mp[8], mn[8];
#pragma unroll
        for (int i = 0; i < 8; i++) { mp[i] = -3.0e38f; mn[i] = 3.0e38f; }
#pragma unroll
        for (int mt = 0; mt < 4; mt++)
#pragma unroll
            for (int h = 0; h < 2; h++) {
                const int ri = mt * 2 + h;
#pragma unroll
                for (int nt = 0; nt < 4; nt++)
#pragma unroll
                    for (int e = 0; e < 2; e++) {
                        const int ci = nt * 2 + e;
                        float v = fmaf(-2.f, acc[mt][nt][h * 2 + e], cn8[ci]);
                        bool same = (rl8[ri] == clab8[ci]);
                        bool self = !offdiag &&
                            (rr8[ri] == warp_n * 32 + nt * 8 + (lane & 3) * 2 + e);
                        if (same) {
                            if (!self) mp[ri] = fmaxf(mp[ri], v);
                        } else {
                            mn[ri] = fminf(mn[ri], v);
                        }
                    }
            }
#pragma unroll
        for (int i = 0; i < 8; i++) {
#pragma unroll
            for (int m = 1; m < 4; m <<= 1) {
                mp[i] = fmaxf(mp[i], __shfl_xor_sync(0xffffffffu, mp[i], m));
                mn[i] = fminf(mn[i], __shfl_xor_sync(0xffffffffu, mn[i], m));
            }
        }
        if ((lane & 3) == 0) {
#pragma unroll
            for (int i = 0; i < 8; i++) {
                if (mp[i] > -2.9e38f) atomicMax(&sMp[rr8[i]], f2i(mp[i]));
                if (mn[i] <  2.9e38f) atomicMin(&sMn[rr8[i]], f2i(mn[i]));
            }
        }

        // --- column-wise mining (off-diagonal only): v' = rn - 2*dot ---
        if (offdiag) {
            float mpc[8], mnc[8];
#pragma unroll
            for (int i = 0; i < 8; i++) { mpc[i] = -3.0e38f; mnc[i] = 3.0e38f; }
#pragma unroll
            for (int nt = 0; nt < 4; nt++)
#pragma unroll
                for (int e = 0; e < 2; e++) {
                    const int ci = nt * 2 + e;
#pragma unroll
                    for (int mt = 0; mt < 4; mt++)
#pragma unroll
                        for (int h = 0; h < 2; h++) {
                            const int ri = mt * 2 + h;
                            float v = fmaf(-2.f, acc[mt][nt][h * 2 + e], rn8[ri]);
                            if (rl8[ri] == clab8[ci]) mpc[ci] = fmaxf(mpc[ci], v);
                            else                       mnc[ci] = fminf(mnc[ci], v);
                        }
                }
#pragma unroll
            for (int i = 0; i < 8; i++) {
#pragma unroll
                for (int m = 4; m < 32; m <<= 1) {
                    mpc[i] = fmaxf(mpc[i], __shfl_xor_sync(0xffffffffu, mpc[i], m));
                    mnc[i] = fminf(mnc[i], __shfl_xor_sync(0xffffffffu, mnc[i], m));
                }
            }
            if (lane < 4) {
#pragma unroll
                for (int nt = 0; nt < 4; nt++)
#pragma unroll
                    for (int e = 0; e < 2; e++) {
                        int cc = warp_n * 32 + nt * 8 + lane * 2 + e;
                        const int ci = nt * 2 + e;
                        if (mpc[ci] > -2.9e38f) atomicMax(&sMp2[cc], f2i(mpc[ci]));
                        if (mnc[ci] <  2.9e38f) atomicMin(&sMn2[cc], f2i(mnc[ci]));
                    }
            }
        }
    }
    __syncthreads();
    if (tid < BM) {
        if (sMp[tid] != INT_MIN) atomicMax(&g_maxpos_i[rowBase + tid], sMp[tid]);
        if (sMn[tid] != INT_MAX) atomicMin(&g_minneg_i[rowBase + tid], sMn[tid]);
        if (offdiag) {
            if (sMp2[tid] != INT_MIN) atomicMax(&g_maxpos_i[colBase + tid], sMp2[tid]);
            if (sMn2[tid] != INT_MAX) atomicMin(&g_minneg_i[colBase + tid], sMn2[tid]);
        }
    }
}

// ---------------------------------------------------------------------------
// Finalize: per-row sqrt + margin, deterministic two-phase mean
// ---------------------------------------------------------------------------
__global__ void finalize1_kernel() {
    __shared__ float ssum[256];
    int t = threadIdx.x;
    int r = blockIdx.x * 256 + t;
    float rn = g_norms[r];
    int ep = g_maxpos_i[r];
    int en = g_minneg_i[r];
    float ap = (ep == INT_MIN) ? 0.f : sqrtf(fmaxf(rn + i2f(ep), 0.f));
    float an = (en == INT_MAX) ? 1e6f : sqrtf(fmaxf(rn + i2f(en), 0.f));
    ssum[t] = fmaxf(0.f, 0.3f + ap - an);
    __syncthreads();
    for (int off = 128; off > 0; off >>= 1) {
        if (t < off) ssum[t] += ssum[t + off];
        __syncthreads();
    }
    if (t == 0) g_partial[blockIdx.x] = ssum[0];
}
__global__ void finalize2_kernel(float* __restrict__ out) {
    float v = g_partial[threadIdx.x];
#pragma unroll
    for (int m = 16; m > 0; m >>= 1) v += __shfl_xor_sync(0xffffffffu, v, m);
    if (threadIdx.x == 0) out[0] = v / (float)N;
}

// ---------------------------------------------------------------------------
extern "C" void kernel_launch(void* const* d_in, const int* in_sizes, int n_in,
                              void* d_out, int out_size) {
    const float* feat = (const float*)d_in[0];
    const int* labels = (const int*)d_in[1];
    float* out = (float*)d_out;

    convert_kernel<<<(N * D / 4 + 255) / 256, 256>>>(feat);
    norms_init_kernel<<<(N * 32 + 255) / 256, 256>>>(feat);
    gram_kernel<<<NBLOCKS, THREADS>>>(labels);
    finalize1_kernel<<<N / 256, 256>>>();
    finalize2_kernel<<<1, 32>>>(out);
}

// round 8
// speedup vs baseline: 4.1461x; 1.3442x over previous
#include <cuda_runtime.h>
#include <cuda_fp16.h>
#include <cstdint>

#define N 8192
#define D 256
#define KE 256              // pure fp16 hi.hi
#define BM 128
#define BN 128
#define BK 32
#define THREADS 256
#define ITERS (KE / BK)     // 8
#define NTILE (N / BM)      // 64
#define NBLOCKS (NTILE * (NTILE + 1) / 2)   // 2080

// ---------------------------------------------------------------------------
__device__ __half g_hi[N * D];
__device__ float g_norms[N];
__device__ int   g_maxpos_i[N];          // encoded floats, INT_MIN = none
__device__ int   g_minneg_i[N];          // encoded floats, INT_MAX = none

__device__ __forceinline__ int f2i(float f) {
    int i = __float_as_int(f);
    return i >= 0 ? i : (i ^ 0x7fffffff);
}
__device__ __forceinline__ float i2f(int i) {
    return __int_as_float(i >= 0 ? i : (i ^ 0x7fffffff));
}
__device__ __forceinline__ uint32_t smem_u32(const void* p) {
    uint32_t a;
    asm("{ .reg .u64 t; cvta.to.shared.u64 t, %1; cvt.u32.u64 %0, t; }"
        : "=r"(a) : "l"(p));
    return a;
}
__device__ __forceinline__ void cp16(uint32_t s, const void* g) {
    asm volatile("cp.async.cg.shared.global [%0], [%1], 16;\n"
                 :: "r"(s), "l"(g) : "memory");
}
#define CP_COMMIT() asm volatile("cp.async.commit_group;" ::: "memory")
#define CP_WAIT(n)  asm volatile("cp.async.wait_group %0;" :: "n"(n) : "memory")

#define LDSM_X4(r0, r1, r2, r3, a)                                            \
    asm volatile("ldmatrix.sync.aligned.m8n8.x4.shared.b16 {%0,%1,%2,%3}, [%4];" \
                 : "=r"(r0), "=r"(r1), "=r"(r2), "=r"(r3) : "r"(a))

#define MMA_F16(c, a0, a1, a2, a3, b0, b1)                                    \
    asm volatile(                                                             \
        "mma.sync.aligned.m16n8k16.row.col.f32.f16.f16.f32 "                  \
        "{%0,%1,%2,%3}, {%4,%5,%6,%7}, {%8,%9}, {%0,%1,%2,%3};"               \
        : "+f"((c)[0]), "+f"((c)[1]), "+f"((c)[2]), "+f"((c)[3])              \
        : "r"(a0), "r"(a1), "r"(a2), "r"(a3), "r"(b0), "r"(b1))

// ---------------------------------------------------------------------------
// Prep (fused): warp per row — fp16 convert + exact fp32 norm + init
// ---------------------------------------------------------------------------
__global__ void prep_kernel(const float* __restrict__ feat) {
    int gtid = blockIdx.x * blockDim.x + threadIdx.x;
    int row = gtid >> 5;
    int lane = gtid & 31;
    if (row >= N) return;
    const float4* f = reinterpret_cast<const float4*>(feat + (size_t)row * D);
    float4 v0 = f[lane * 2];
    float4 v1 = f[lane * 2 + 1];
    float s = v0.x * v0.x + v0.y * v0.y + v0.z * v0.z + v0.w * v0.w
            + v1.x * v1.x + v1.y * v1.y + v1.z * v1.z + v1.w * v1.w;
    __half h[8];
    h[0] = __float2half_rn(v0.x); h[1] = __float2half_rn(v0.y);
    h[2] = __float2half_rn(v0.z); h[3] = __float2half_rn(v0.w);
    h[4] = __float2half_rn(v1.x); h[5] = __float2half_rn(v1.y);
    h[6] = __float2half_rn(v1.z); h[7] = __float2half_rn(v1.w);
    *reinterpret_cast<uint4*>(g_hi + (size_t)row * D + lane * 8) =
        *reinterpret_cast<uint4*>(h);
#pragma unroll
    for (int m = 16; m > 0; m >>= 1) s += __shfl_xor_sync(0xffffffffu, s, m);
    if (lane == 0) {
        g_norms[row] = s;
        g_maxpos_i[row] = INT_MIN;
        g_minneg_i[row] = INT_MAX;
    }
}

// ---------------------------------------------------------------------------
// Main: symmetric HMMA Gram (upper-tri tiles only) + dual-orientation mining
// ---------------------------------------------------------------------------
#define LDA 40

__global__ __launch_bounds__(THREADS, 2)
void gram_kernel(const int* __restrict__ labels) {
    __shared__ __half As[2][BM * LDA];
    __shared__ __half Bs[2][BN * LDA];
    __shared__ int   sColLab[BN];
    __shared__ float sColNorm[BN];
    __shared__ int   sRowLab[BM];
    __shared__ float sRowNorm[BM];
    __shared__ int   sMp[BM],  sMn[BM];    // row-wise results (tile I rows)
    __shared__ int   sMp2[BN], sMn2[BN];   // col-wise results (tile J rows)

    // decode upper-triangular tile pair (I <= J)
    int t = blockIdx.x;
    int I = 0;
    while (t >= NTILE - I) { t -= NTILE - I; I++; }
    const int J = I + t;
    const bool offdiag = (I != J);
    const int rowBase = I * BM;
    const int colBase = J * BN;

    const int tid = threadIdx.x;
    const int lane = tid & 31;
    const int wid = tid >> 5;
    const int warp_m = wid >> 2;          // 0..1  (64 rows each)
    const int warp_n = wid & 3;           // 0..3  (32 cols each)

    if (tid < BM) {
        sColLab[tid]  = labels[colBase + tid];
        sColNorm[tid] = g_norms[colBase + tid];
        sRowLab[tid]  = labels[rowBase + tid];
        sRowNorm[tid] = g_norms[rowBase + tid];
        sMp[tid] = INT_MIN;  sMn[tid] = INT_MAX;
        sMp2[tid] = INT_MIN; sMn2[tid] = INT_MAX;
    }

    const uint32_t sA[2] = {smem_u32(&As[0][0]), smem_u32(&As[1][0])};
    const uint32_t sB[2] = {smem_u32(&Bs[0][0]), smem_u32(&Bs[1][0])};

    const uint32_t aOff = ((warp_m * 64 + (lane & 15)) * LDA + (lane >> 4) * 8) * 2;
    const uint32_t bOff = ((warp_n * 32 + (lane & 7) + ((lane >> 4) & 1) * 8) * LDA
                          + ((lane >> 3) & 1) * 8) * 2;

    const __half* ga = g_hi + (size_t)rowBase * D;
    const __half* gb = g_hi + (size_t)colBase * D;

    auto load_stage = [&](int kt, int buf) {
        const int k0 = kt * BK;
#pragma unroll
        for (int i = 0; i < 2; i++) {
            int idx = tid + i * THREADS;
            int r = idx >> 2, c = idx & 3;
            cp16(sA[buf] + (r * LDA + c * 8) * 2, ga + (size_t)r * D + k0 + c * 8);
        }
#pragma unroll
        for (int i = 0; i < 2; i++) {
            int idx = tid + i * THREADS;
            int r = idx >> 2, c = idx & 3;
            cp16(sB[buf] + (r * LDA + c * 8) * 2, gb + (size_t)r * D + k0 + c * 8);
        }
        CP_COMMIT();
    };

    float acc[4][4][4];
#pragma unroll
    for (int i = 0; i < 4; i++)
#pragma unroll
        for (int j = 0; j < 4; j++)
#pragma unroll
            for (int e = 0; e < 4; e++) acc[i][j][e] = 0.f;

    load_stage(0, 0);

    for (int it = 0; it < ITERS; ++it) {
        const int buf = it & 1;
        if (it + 1 < ITERS) load_stage(it + 1, buf ^ 1);
        if (it + 1 < ITERS) { CP_WAIT(1); } else { CP_WAIT(0); }
        __syncthreads();

#pragma unroll
        for (int ks = 0; ks < 2; ks++) {
            uint32_t aF[4][4], bF[2][4];
#pragma unroll
            for (int mt = 0; mt < 4; mt++)
                LDSM_X4(aF[mt][0], aF[mt][1], aF[mt][2], aF[mt][3],
                        sA[buf] + aOff + mt * (16 * LDA * 2) + ks * 32);
#pragma unroll
            for (int ng = 0; ng < 2; ng++)
                LDSM_X4(bF[ng][0], bF[ng][1], bF[ng][2], bF[ng][3],
                        sB[buf] + bOff + ng * (16 * LDA * 2) + ks * 32);
#pragma unroll
            for (int mt = 0; mt < 4; mt++) {
#pragma unroll
                for (int nt = 0; nt < 4; nt++) {
                    const int ng = nt >> 1;
                    const int hi = (nt & 1) << 1;
                    MMA_F16(acc[mt][nt], aF[mt][0], aF[mt][1], aF[mt][2], aF[mt][3],
                            bF[ng][hi], bF[ng][hi + 1]);
                }
            }
        }
        __syncthreads();
    }

    // ---- epilogue ----
    {
        float cn8[8]; int clab8[8];
#pragma unroll
        for (int nt = 0; nt < 4; nt++)
#pragma unroll
            for (int e = 0; e < 2; e++) {
                int cc = warp_n * 32 + nt * 8 + (lane & 3) * 2 + e;
                cn8[nt * 2 + e] = sColNorm[cc];
                clab8[nt * 2 + e] = sColLab[cc];
            }
        int rl8[8]; float rn8[8]; int rr8[8];
#pragma unroll
        for (int mt = 0; mt < 4; mt++)
#pragma unroll
            for (int h = 0; h < 2; h++) {
                int rr = warp_m * 64 + mt * 16 + (lane >> 2) + h * 8;
                rr8[mt * 2 + h] = rr;
                rl8[mt * 2 + h] = sRowLab[rr];
                rn8[mt * 2 + h] = sRowNorm[rr];
            }

        // --- row-wise mining: v = cn - 2*dot ---
        float mp[8], mn[8];
#pragma unroll
        for (int i = 0; i < 8; i++) { mp[i] = -3.0e38f; mn[i] = 3.0e38f; }
#pragma unroll
        for (int mt = 0; mt < 4; mt++)
#pragma unroll
            for (int h = 0; h < 2; h++) {
                const int ri = mt * 2 + h;
#pragma unroll
                for (int nt = 0; nt < 4; nt++)
#pragma unroll
                    for (int e = 0; e < 2; e++) {
                        const int ci = nt * 2 + e;
                        float v = fmaf(-2.f, acc[mt][nt][h * 2 + e], cn8[ci]);
                        bool same = (rl8[ri] == clab8[ci]);
                        bool self = !offdiag &&
                            (rr8[ri] == warp_n * 32 + nt * 8 + (lane & 3) * 2 + e);
                        if (same) {
                            if (!self) mp[ri] = fmaxf(mp[ri], v);
                        } else {
                            mn[ri] = fminf(mn[ri], v);
                        }
                    }
            }
#pragma unroll
        for (int i = 0; i < 8; i++) {
#pragma unroll
            for (int m = 1; m < 4; m <<= 1) {
                mp[i] = fmaxf(mp[i], __shfl_xor_sync(0xffffffffu, mp[i], m));
                mn[i] = fminf(mn[i], __shfl_xor_sync(0xffffffffu, mn[i], m));
            }
        }
        if ((lane & 3) == 0) {
#pragma unroll
            for (int i = 0; i < 8; i++) {
                if (mp[i] > -2.9e38f) atomicMax(&sMp[rr8[i]], f2i(mp[i]));
                if (mn[i] <  2.9e38f) atomicMin(&sMn[rr8[i]], f2i(mn[i]));
            }
        }

        // --- column-wise mining (off-diagonal only): v' = rn - 2*dot ---
        if (offdiag) {
            float mpc[8], mnc[8];
#pragma unroll
            for (int i = 0; i < 8; i++) { mpc[i] = -3.0e38f; mnc[i] = 3.0e38f; }
#pragma unroll
            for (int nt = 0; nt < 4; nt++)
#pragma unroll
                for (int e = 0; e < 2; e++) {
                    const int ci = nt * 2 + e;
#pragma unroll
                    for (int mt = 0; mt < 4; mt++)
#pragma unroll
                        for (int h = 0; h < 2; h++) {
                            const int ri = mt * 2 + h;
                            float v = fmaf(-2.f, acc[mt][nt][h * 2 + e], rn8[ri]);
                            if (rl8[ri] == clab8[ci]) mpc[ci] = fmaxf(mpc[ci], v);
                            else                       mnc[ci] = fminf(mnc[ci], v);
                        }
                }
#pragma unroll
            for (int i = 0; i < 8; i++) {
#pragma unroll
                for (int m = 4; m < 32; m <<= 1) {
                    mpc[i] = fmaxf(mpc[i], __shfl_xor_sync(0xffffffffu, mpc[i], m));
                    mnc[i] = fminf(mnc[i], __shfl_xor_sync(0xffffffffu, mnc[i], m));
                }
            }
            if (lane < 4) {
#pragma unroll
                for (int nt = 0; nt < 4; nt++)
#pragma unroll
                    for (int e = 0; e < 2; e++) {
                        int cc = warp_n * 32 + nt * 8 + lane * 2 + e;
                        const int ci = nt * 2 + e;
                        if (mpc[ci] > -2.9e38f) atomicMax(&sMp2[cc], f2i(mpc[ci]));
                        if (mnc[ci] <  2.9e38f) atomicMin(&sMn2[cc], f2i(mnc[ci]));
                    }
            }
        }
    }
    __syncthreads();
    if (tid < BM) {
        if (sMp[tid] != INT_MIN) atomicMax(&g_maxpos_i[rowBase + tid], sMp[tid]);
        if (sMn[tid] != INT_MAX) atomicMin(&g_minneg_i[rowBase + tid], sMn[tid]);
        if (offdiag) {
            if (sMp2[tid] != INT_MIN) atomicMax(&g_maxpos_i[colBase + tid], sMp2[tid]);
            if (sMn2[tid] != INT_MAX) atomicMin(&g_minneg_i[colBase + tid], sMn2[tid]);
        }
    }
}

// ---------------------------------------------------------------------------
// Finalize (single block): per-row sqrt + margin, deterministic mean
// ---------------------------------------------------------------------------
__global__ void finalize_kernel(float* __restrict__ out) {
    __shared__ float ssum[256];
    int t = threadIdx.x;
    float s = 0.f;
    for (int r = t; r < N; r += 256) {
        float rn = g_norms[r];
        int ep = g_maxpos_i[r];
        int en = g_minneg_i[r];
        float ap = (ep == INT_MIN) ? 0.f : sqrtf(fmaxf(rn + i2f(ep), 0.f));
        float an = (en == INT_MAX) ? 1e6f : sqrtf(fmaxf(rn + i2f(en), 0.f));
        s += fmaxf(0.f, 0.3f + ap - an);
    }
    ssum[t] = s;
    __syncthreads();
    for (int off = 128; off > 0; off >>= 1) {
        if (t < off) ssum[t] += ssum[t + off];
        __syncthreads();
    }
    if (t == 0) out[0] = ssum[0] / (float)N;
}

// ---------------------------------------------------------------------------
extern "C" void kernel_launch(void* const* d_in, const int* in_sizes, int n_in,
                              void* d_out, int out_size) {
    const float* feat = (const float*)d_in[0];
    const int* labels = (const int*)d_in[1];
    float* out = (float*)d_out;

    prep_kernel<<<(N * 32 + 255) / 256, 256>>>(feat);
    gram_kernel<<<NBLOCKS, THREADS>>>(labels);
    finalize_kernel<<<1, 256>>>(out);
}